// round 1
// baseline (speedup 1.0000x reference)
#include <cuda_runtime.h>

namespace {
constexpr int THREADS = 256;
constexpr int S    = 32;          // samples per CTA
constexpr int T    = 10;
constexpr int DIN  = 16;
constexpr int H    = 64;
constexpr int G    = 4 * H;       // 256 gate columns
constexpr int DMLP = 30;
constexpr int DOUT = 4;
constexpr int BATCH = 65536;
constexpr int NCTA  = BATCH / S;  // 2048
constexpr int XROW  = 36;         // padded row stride (floats) for x tile

// shared memory layout (float offsets)
constexpr int OFF_UP  = 0;                          // 64*256  (U1 in phase1, U2 in phase2)
constexpr int OFF_W1P = OFF_UP  + H * G;            // 16*256
constexpr int OFF_W2P = OFF_W1P + DIN * G;          // 30*256
constexpr int OFF_WDS = OFF_W2P + DMLP * G;         // 64*32 (Wd padded 30->32)
constexpr int OFF_WFS = OFF_WDS + H * 32;           // 64*4
constexpr int OFF_B1P = OFF_WFS + H * DOUT;         // 256
constexpr int OFF_B2P = OFF_B1P + G;                // 256
constexpr int OFF_BDS = OFF_B2P + G;                // 32
constexpr int OFF_BFS = OFF_BDS + 32;               // 4
constexpr int OFF_HS  = OFF_BFS + 4;                // 64*32 h-state tile [unit][sample]
constexpr int OFF_XSH = OFF_HS  + H * S;            // 160 rows * 36
constexpr int OFF_DSH = OFF_XSH + T * DIN * XROW;   // 300 rows * 32
constexpr int SMEM_FLOATS = OFF_DSH + T * DMLP * S;
constexpr int SMEM_BYTES  = SMEM_FLOATS * 4;        // ~193.7 KB
static_assert(OFF_HS % 4 == 0 && OFF_XSH % 4 == 0 && OFF_DSH % 4 == 0, "float4 alignment");
} // namespace

// accurate-enough activations: EX2 + RCP based, rel err ~1e-7
__device__ __forceinline__ float sigm(float x) {
    return __fdividef(1.0f, 1.0f + __expf(-x));
}
__device__ __forceinline__ float tanh_acc(float x) {
    // tanh(x) = 2*sigmoid(2x) - 1
    return __fdividef(2.0f, 1.0f + __expf(-2.0f * x)) - 1.0f;
}

// gate-interleaved column permutation:
// shared column p -> original gate column ((p&7)>>1)*64 + (p>>3)*2 + (p&1)
__device__ __forceinline__ int pcol(int p) {
    const int ug = p >> 3, r = p & 7;
    return ((r >> 1) << 6) + (ug << 1) + (r & 1);
}

// acc[s][r] += sum_k a[k][sg4+s] * w[k][ug8+r]   (register-blocked 4x8 tile)
__device__ __forceinline__ void gemm_acc(const float* __restrict__ a, const int astride,
                                         const float* __restrict__ w, const int K,
                                         const int sg4, const int ug8, float acc[4][8]) {
#pragma unroll 4
    for (int k = 0; k < K; ++k) {
        const float4 hv = *reinterpret_cast<const float4*>(a + k * astride + sg4);
        const float4 w0 = *reinterpret_cast<const float4*>(w + k * G + ug8);
        const float4 w1 = *reinterpret_cast<const float4*>(w + k * G + ug8 + 4);
        const float hvv[4] = {hv.x, hv.y, hv.z, hv.w};
        const float ww[8]  = {w0.x, w0.y, w0.z, w0.w, w1.x, w1.y, w1.z, w1.w};
#pragma unroll
        for (int s = 0; s < 4; ++s)
#pragma unroll
            for (int r = 0; r < 8; ++r)
                acc[s][r] = fmaf(hvv[s], ww[r], acc[s][r]);
    }
}

__global__ void __launch_bounds__(THREADS, 1)
rnn_kernel(const float* __restrict__ x,
           const float* __restrict__ W1, const float* __restrict__ U1, const float* __restrict__ b1,
           const float* __restrict__ Wd, const float* __restrict__ bd,
           const float* __restrict__ W2, const float* __restrict__ U2, const float* __restrict__ b2,
           const float* __restrict__ Wf, const float* __restrict__ bf,
           float* __restrict__ out)
{
    extern __shared__ float sm[];
    float* Up  = sm + OFF_UP;
    float* W1p = sm + OFF_W1P;
    float* W2p = sm + OFF_W2P;
    float* Wds = sm + OFF_WDS;
    float* Wfs = sm + OFF_WFS;
    float* b1p = sm + OFF_B1P;
    float* b2p = sm + OFF_B2P;
    float* bds = sm + OFF_BDS;
    float* bfs = sm + OFF_BFS;
    float* hs  = sm + OFF_HS;
    float* xsh = sm + OFF_XSH;
    float* dsh = sm + OFF_DSH;

    const int tid = threadIdx.x;
    const int sg4 = (tid & 7) << 2;   // 8 sample-groups * 4 samples
    const int ug8 = (tid >> 3) << 3;  // 32 unit-groups  * (2 units x 4 gates)

    // ---- stage weights (permuted) + x tile into shared ----
    for (int idx = tid; idx < H * G; idx += THREADS) {
        const int k = idx >> 8, p = idx & 255;
        Up[idx] = U1[(k << 8) + pcol(p)];
    }
    for (int idx = tid; idx < DIN * G; idx += THREADS) {
        const int k = idx >> 8, p = idx & 255;
        W1p[idx] = W1[(k << 8) + pcol(p)];
    }
    for (int idx = tid; idx < DMLP * G; idx += THREADS) {
        const int k = idx >> 8, p = idx & 255;
        W2p[idx] = W2[(k << 8) + pcol(p)];
    }
    for (int idx = tid; idx < G; idx += THREADS) {
        const int c0 = pcol(idx);
        b1p[idx] = b1[c0];
        b2p[idx] = b2[c0];
    }
    for (int idx = tid; idx < H * 32; idx += THREADS) {
        const int k = idx >> 5, j = idx & 31;
        Wds[idx] = (j < DMLP) ? Wd[k * DMLP + j] : 0.0f;
    }
    if (tid < H * DOUT) Wfs[tid] = Wf[tid];
    if (tid < 32)  bds[tid] = (tid < DMLP) ? bd[tid] : 0.0f;
    if (tid < DOUT) bfs[tid] = bf[tid];

    const float* xg = x + (size_t)blockIdx.x * (S * T * DIN);
    for (int idx = tid; idx < S * T * DIN; idx += THREADS) {
        const int s = idx / (T * DIN);
        const int r = idx - s * (T * DIN);     // r = t*16 + k
        xsh[r * XROW + s] = xg[idx];
    }
    __syncthreads();

    float bgate[8];
#pragma unroll
    for (int r = 0; r < 8; ++r) bgate[r] = b1p[ug8 + r];

    float cst[4][2] = {{0.f,0.f},{0.f,0.f},{0.f,0.f},{0.f,0.f}};

    // ================= phase 1: LSTM1 (tanh) + Dense =================
    for (int t = 0; t < T; ++t) {
        float acc[4][8];
#pragma unroll
        for (int s = 0; s < 4; ++s)
#pragma unroll
            for (int r = 0; r < 8; ++r) acc[s][r] = bgate[r];

        gemm_acc(xsh + t * DIN * XROW, XROW, W1p, DIN, sg4, ug8, acc);
        if (t > 0) gemm_acc(hs, S, Up, H, sg4, ug8, acc);   // h0 = 0: skip

        float hh[4][2];
#pragma unroll
        for (int s = 0; s < 4; ++s)
#pragma unroll
            for (int e = 0; e < 2; ++e) {
                const float ig = sigm(acc[s][0 + e]);
                const float fg = sigm(acc[s][2 + e]);
                const float gg = tanh_acc(acc[s][4 + e]);
                const float og = sigm(acc[s][6 + e]);
                const float cc = fmaf(fg, cst[s][e], ig * gg);
                cst[s][e] = cc;
                hh[s][e] = og * tanh_acc(cc);
            }
        __syncthreads();   // all readers of old hs done
#pragma unroll
        for (int s = 0; s < 4; ++s)
#pragma unroll
            for (int e = 0; e < 2; ++e)
                hs[((ug8 >> 2) + e) * S + sg4 + s] = hh[s][e];
        __syncthreads();   // new hs visible

        // Dense: d[t] = h1[t] @ Wd + bd  -> dsh
        for (int idx = tid; idx < S * DMLP; idx += THREADS) {
            const int s = idx & 31, j = idx >> 5;
            float a = bds[j];
#pragma unroll 8
            for (int k = 0; k < H; ++k)
                a = fmaf(hs[k * S + s], Wds[k * 32 + j], a);
            dsh[(t * DMLP + j) * S + s] = a;
        }
    }

    // ================= phase boundary: swap U1 -> U2 =================
    __syncthreads();
    for (int idx = tid; idx < H * G; idx += THREADS) {
        const int k = idx >> 8, p = idx & 255;
        Up[idx] = U2[(k << 8) + pcol(p)];
    }
#pragma unroll
    for (int r = 0; r < 8; ++r) bgate[r] = b2p[ug8 + r];
#pragma unroll
    for (int s = 0; s < 4; ++s) { cst[s][0] = 0.0f; cst[s][1] = 0.0f; }
    __syncthreads();

    // ================= phase 2: LSTM2 (relu) =================
    for (int t = 0; t < T; ++t) {
        float acc[4][8];
#pragma unroll
        for (int s = 0; s < 4; ++s)
#pragma unroll
            for (int r = 0; r < 8; ++r) acc[s][r] = bgate[r];

        gemm_acc(dsh + t * DMLP * S, S, W2p, DMLP, sg4, ug8, acc);
        if (t > 0) gemm_acc(hs, S, Up, H, sg4, ug8, acc);

        float hh[4][2];
#pragma unroll
        for (int s = 0; s < 4; ++s)
#pragma unroll
            for (int e = 0; e < 2; ++e) {
                const float ig = sigm(acc[s][0 + e]);
                const float fg = sigm(acc[s][2 + e]);
                const float gg = fmaxf(acc[s][4 + e], 0.0f);   // relu activation
                const float og = sigm(acc[s][6 + e]);
                const float cc = fmaf(fg, cst[s][e], ig * gg);
                cst[s][e] = cc;
                hh[s][e] = og * fmaxf(cc, 0.0f);
            }
        __syncthreads();
#pragma unroll
        for (int s = 0; s < 4; ++s)
#pragma unroll
            for (int e = 0; e < 2; ++e)
                hs[((ug8 >> 2) + e) * S + sg4 + s] = hh[s][e];
        __syncthreads();
    }

    // ================= head: out = h2_last @ Wf + bf =================
    float* outg = out + (size_t)blockIdx.x * (S * DOUT);
    for (int idx = tid; idx < S * DOUT; idx += THREADS) {
        const int s = idx & 31, j = idx >> 5;
        float a = bfs[j];
#pragma unroll 8
        for (int k = 0; k < H; ++k)
            a = fmaf(hs[k * S + s], Wfs[k * DOUT + j], a);
        outg[s * DOUT + j] = a;
    }
}

extern "C" void kernel_launch(void* const* d_in, const int* in_sizes, int n_in,
                              void* d_out, int out_size) {
    (void)in_sizes; (void)n_in; (void)out_size;
    const float* x  = (const float*)d_in[0];
    const float* W1 = (const float*)d_in[1];
    const float* U1 = (const float*)d_in[2];
    const float* b1 = (const float*)d_in[3];
    const float* Wd = (const float*)d_in[4];
    const float* bd = (const float*)d_in[5];
    const float* W2 = (const float*)d_in[6];
    const float* U2 = (const float*)d_in[7];
    const float* b2 = (const float*)d_in[8];
    const float* Wf = (const float*)d_in[9];
    const float* bf = (const float*)d_in[10];
    float* out = (float*)d_out;

    cudaFuncSetAttribute(rnn_kernel, cudaFuncAttributeMaxDynamicSharedMemorySize, SMEM_BYTES);
    rnn_kernel<<<NCTA, THREADS, SMEM_BYTES>>>(x, W1, U1, b1, Wd, bd, W2, U2, b2, Wf, bf, out);
}

// round 2
// speedup vs baseline: 1.1253x; 1.1253x over previous
#include <cuda_runtime.h>

namespace {
constexpr int THREADS = 256;
constexpr int S    = 64;          // samples per CTA
constexpr int T    = 10;
constexpr int DIN  = 16;
constexpr int H    = 64;
constexpr int G    = 4 * H;       // 256 gate columns
constexpr int DMLP = 30;
constexpr int DOUT = 4;
constexpr int BATCH = 65536;
constexpr int NCTA  = BATCH / S;  // 1024

// shared memory layout (float offsets)
constexpr int OFF_UP  = 0;                      // 64*256 (U1 phase1 / U2 phase2)
constexpr int OFF_W1P = OFF_UP  + H * G;        // 16*256
constexpr int OFF_W2P = OFF_W1P + DIN * G;      // 30*256
constexpr int OFF_WDS = OFF_W2P + DMLP * G;     // 64*32 (Wd padded 30->32)
constexpr int OFF_WFS = OFF_WDS + H * 32;       // 64*4
constexpr int OFF_B1P = OFF_WFS + H * DOUT;     // 256
constexpr int OFF_B2P = OFF_B1P + G;            // 256
constexpr int OFF_BDS = OFF_B2P + G;            // 32
constexpr int OFF_BFS = OFF_BDS + 32;           // 4
constexpr int OFF_HS  = OFF_BFS + 4;            // 64*64 h-state [unit][sample]
constexpr int OFF_XSH = OFF_HS  + H * S;        // 2 x 16 x 64 (double-buffered x[t])
constexpr int OFF_DSH = OFF_XSH + 2 * DIN * S;  // 300 x 64
constexpr int SMEM_FLOATS = OFF_DSH + T * DMLP * S;   // 56356
constexpr int SMEM_BYTES  = SMEM_FLOATS * 4;          // 225424 B
static_assert(OFF_HS % 4 == 0 && OFF_XSH % 4 == 0 && OFF_DSH % 4 == 0, "float4 alignment");
} // namespace

using u64 = unsigned long long;

// packed f32x2 helpers (Blackwell fma pipe does 2 fp32 FMAs per issue)
#define PACK2(d, lo, hi)  asm("mov.b64 %0, {%1, %2};" : "=l"(d) : "f"(lo), "f"(hi))
#define UNPACK2(lo, hi, s) asm("mov.b64 {%0, %1}, %2;" : "=f"(lo), "=f"(hi) : "l"(s))
#define FMA2(d, a, b, c)  asm("fma.rn.f32x2 %0, %1, %2, %3;" : "=l"(d) : "l"(a), "l"(b), "l"(c))

// accurate activations: EX2 + RCP based, rel err ~1e-7
__device__ __forceinline__ float sigm(float x) {
    return __fdividef(1.0f, 1.0f + __expf(-x));
}
__device__ __forceinline__ float tanh_acc(float x) {
    return __fdividef(2.0f, 1.0f + __expf(-2.0f * x)) - 1.0f;
}

// gate-interleaved column permutation:
// shared column p -> original gate column ((p&7)>>1)*64 + (p>>3)*2 + (p&1)
__device__ __forceinline__ int pcol(int p) {
    const int ug = p >> 3, r = p & 7;
    return ((r >> 1) << 6) + (ug << 1) + (r & 1);
}

// acc[s][r2] += (a[k][sg8+s] dup2) * (w[k][ug8+2r2], w[k][ug8+2r2+1])
// a rows have stride 64 floats; w rows stride 256.
__device__ __forceinline__ void gemm2(const float* __restrict__ a,
                                      const float* __restrict__ w,
                                      const int K, const int sg8, const int ug8,
                                      u64 acc[8][4]) {
#pragma unroll 2
    for (int k = 0; k < K; ++k) {
        const float4 h0 = *reinterpret_cast<const float4*>(a + k * 64 + sg8);
        const float4 h1 = *reinterpret_cast<const float4*>(a + k * 64 + sg8 + 4);
        const float4 w0 = *reinterpret_cast<const float4*>(w + k * G + ug8);
        const float4 w1 = *reinterpret_cast<const float4*>(w + k * G + ug8 + 4);
        u64 wp[4];
        PACK2(wp[0], w0.x, w0.y); PACK2(wp[1], w0.z, w0.w);
        PACK2(wp[2], w1.x, w1.y); PACK2(wp[3], w1.z, w1.w);
        const float hv[8] = {h0.x, h0.y, h0.z, h0.w, h1.x, h1.y, h1.z, h1.w};
        u64 hd[8];
#pragma unroll
        for (int s = 0; s < 8; ++s) PACK2(hd[s], hv[s], hv[s]);
#pragma unroll
        for (int s = 0; s < 8; ++s)
#pragma unroll
            for (int r = 0; r < 4; ++r)
                FMA2(acc[s][r], hd[s], wp[r], acc[s][r]);
    }
}

__global__ void __launch_bounds__(THREADS, 1)
rnn_kernel(const float* __restrict__ x,
           const float* __restrict__ W1, const float* __restrict__ U1, const float* __restrict__ b1,
           const float* __restrict__ Wd, const float* __restrict__ bd,
           const float* __restrict__ W2, const float* __restrict__ U2, const float* __restrict__ b2,
           const float* __restrict__ Wf, const float* __restrict__ bf,
           float* __restrict__ out)
{
    extern __shared__ float sm[];
    float* Up  = sm + OFF_UP;
    float* W1p = sm + OFF_W1P;
    float* W2p = sm + OFF_W2P;
    float* Wds = sm + OFF_WDS;
    float* Wfs = sm + OFF_WFS;
    float* b1p = sm + OFF_B1P;
    float* b2p = sm + OFF_B2P;
    float* bds = sm + OFF_BDS;
    float* bfs = sm + OFF_BFS;
    float* hs  = sm + OFF_HS;
    float* xsh = sm + OFF_XSH;
    float* dsh = sm + OFF_DSH;

    const int tid = threadIdx.x;
    const int sg8 = (tid & 7) << 3;   // 8 sample-groups * 8 samples = 64
    const int ug8 = (tid >> 3) << 3;  // 32 gate-groups * 8 perm cols = 256

    // ---- stage weights (permuted) into shared ----
    for (int idx = tid; idx < H * G; idx += THREADS) {
        const int k = idx >> 8, p = idx & 255;
        Up[idx] = U1[(k << 8) + pcol(p)];
    }
    for (int idx = tid; idx < DIN * G; idx += THREADS) {
        const int k = idx >> 8, p = idx & 255;
        W1p[idx] = W1[(k << 8) + pcol(p)];
    }
    for (int idx = tid; idx < DMLP * G; idx += THREADS) {
        const int k = idx >> 8, p = idx & 255;
        W2p[idx] = W2[(k << 8) + pcol(p)];
    }
    for (int idx = tid; idx < G; idx += THREADS) {
        const int c0 = pcol(idx);
        b1p[idx] = b1[c0];
        b2p[idx] = b2[c0];
    }
    for (int idx = tid; idx < H * 32; idx += THREADS) {
        const int k = idx >> 5, j = idx & 31;
        Wds[idx] = (j < DMLP) ? Wd[k * DMLP + j] : 0.0f;
    }
    if (tid < H * DOUT) Wfs[tid] = Wf[tid];
    if (tid < 32)  bds[tid] = (tid < DMLP) ? bd[tid] : 0.0f;
    if (tid < DOUT) bfs[tid] = bf[tid];

    // ---- stage x[t=0] into buffer 0 ----
    const float* xg = x + (size_t)blockIdx.x * (S * T * DIN);
    const int xs  = tid & 63;        // sample
    const int xkg = (tid >> 6) << 2; // k group of 4
    {
        const float4 v = *reinterpret_cast<const float4*>(xg + xs * (T * DIN) + xkg);
        xsh[(xkg + 0) * 64 + xs] = v.x;
        xsh[(xkg + 1) * 64 + xs] = v.y;
        xsh[(xkg + 2) * 64 + xs] = v.z;
        xsh[(xkg + 3) * 64 + xs] = v.w;
    }
    __syncthreads();

    u64 bg2[4];
#pragma unroll
    for (int r = 0; r < 4; ++r) PACK2(bg2[r], b1p[ug8 + 2 * r], b1p[ug8 + 2 * r + 1]);

    u64 dbias2;
    const int dj  = tid >> 3;         // dense output col (0..31, >=30 idle)
    const int ds8 = (tid & 7) << 3;   // dense sample group
    {
        const float bj = (dj < DMLP) ? bds[dj] : 0.0f;
        PACK2(dbias2, bj, bj);
    }

    float cst[8][2];
#pragma unroll
    for (int s = 0; s < 8; ++s) { cst[s][0] = 0.0f; cst[s][1] = 0.0f; }

    const int u0 = (tid >> 3) << 1;   // first of this thread's 2 hidden units

    // ================= phase 1: LSTM1 (tanh) + Dense =================
    for (int t = 0; t < T; ++t) {
        // prefetch x[t+1] to registers (hidden behind the GEMMs)
        float4 xr = make_float4(0.f, 0.f, 0.f, 0.f);
        if (t + 1 < T)
            xr = *reinterpret_cast<const float4*>(xg + xs * (T * DIN) + (t + 1) * DIN + xkg);

        u64 acc[8][4];
#pragma unroll
        for (int s = 0; s < 8; ++s)
#pragma unroll
            for (int r = 0; r < 4; ++r) acc[s][r] = bg2[r];

        gemm2(xsh + (t & 1) * (DIN * S), W1p, DIN, sg8, ug8, acc);
        if (t > 0) gemm2(hs, Up, H, sg8, ug8, acc);   // h0 = 0: skip

        float hh0[8], hh1[8];
#pragma unroll
        for (int s = 0; s < 8; ++s) {
            float val[8];
            UNPACK2(val[0], val[1], acc[s][0]);
            UNPACK2(val[2], val[3], acc[s][1]);
            UNPACK2(val[4], val[5], acc[s][2]);
            UNPACK2(val[6], val[7], acc[s][3]);
#pragma unroll
            for (int e = 0; e < 2; ++e) {
                const float ig = sigm(val[0 + e]);
                const float fg = sigm(val[2 + e]);
                const float gg = tanh_acc(val[4 + e]);
                const float og = sigm(val[6 + e]);
                const float cc = fmaf(fg, cst[s][e], ig * gg);
                cst[s][e] = cc;
                const float hv = og * tanh_acc(cc);
                if (e == 0) hh0[s] = hv; else hh1[s] = hv;
            }
        }
        __syncthreads();   // all readers of old hs / xsh[(t+1)&1] done
        *reinterpret_cast<float4*>(hs + u0 * 64 + sg8)           = make_float4(hh0[0], hh0[1], hh0[2], hh0[3]);
        *reinterpret_cast<float4*>(hs + u0 * 64 + sg8 + 4)       = make_float4(hh0[4], hh0[5], hh0[6], hh0[7]);
        *reinterpret_cast<float4*>(hs + (u0 + 1) * 64 + sg8)     = make_float4(hh1[0], hh1[1], hh1[2], hh1[3]);
        *reinterpret_cast<float4*>(hs + (u0 + 1) * 64 + sg8 + 4) = make_float4(hh1[4], hh1[5], hh1[6], hh1[7]);
        if (t + 1 < T) {
            float* xb = xsh + ((t + 1) & 1) * (DIN * S);
            xb[(xkg + 0) * 64 + xs] = xr.x;
            xb[(xkg + 1) * 64 + xs] = xr.y;
            xb[(xkg + 2) * 64 + xs] = xr.z;
            xb[(xkg + 3) * 64 + xs] = xr.w;
        }
        __syncthreads();   // new hs + x visible

        // Dense: d[t] = h1[t] @ Wd + bd  -> dsh (f32x2 over sample pairs)
        if (dj < DMLP) {
            u64 dacc[4];
#pragma unroll
            for (int r = 0; r < 4; ++r) dacc[r] = dbias2;
#pragma unroll 4
            for (int k = 0; k < H; ++k) {
                const float4 h0 = *reinterpret_cast<const float4*>(hs + k * 64 + ds8);
                const float4 h1 = *reinterpret_cast<const float4*>(hs + k * 64 + ds8 + 4);
                const float wv = Wds[k * 32 + dj];
                u64 wd; PACK2(wd, wv, wv);
                u64 hp[4];
                PACK2(hp[0], h0.x, h0.y); PACK2(hp[1], h0.z, h0.w);
                PACK2(hp[2], h1.x, h1.y); PACK2(hp[3], h1.z, h1.w);
#pragma unroll
                for (int r = 0; r < 4; ++r) FMA2(dacc[r], hp[r], wd, dacc[r]);
            }
            float dv[8];
            UNPACK2(dv[0], dv[1], dacc[0]);
            UNPACK2(dv[2], dv[3], dacc[1]);
            UNPACK2(dv[4], dv[5], dacc[2]);
            UNPACK2(dv[6], dv[7], dacc[3]);
            float* drow = dsh + (t * DMLP + dj) * 64 + ds8;
            *reinterpret_cast<float4*>(drow)     = make_float4(dv[0], dv[1], dv[2], dv[3]);
            *reinterpret_cast<float4*>(drow + 4) = make_float4(dv[4], dv[5], dv[6], dv[7]);
        }
    }

    // ================= phase boundary: swap U1 -> U2 =================
    __syncthreads();
    for (int idx = tid; idx < H * G; idx += THREADS) {
        const int k = idx >> 8, p = idx & 255;
        Up[idx] = U2[(k << 8) + pcol(p)];
    }
#pragma unroll
    for (int r = 0; r < 4; ++r) PACK2(bg2[r], b2p[ug8 + 2 * r], b2p[ug8 + 2 * r + 1]);
#pragma unroll
    for (int s = 0; s < 8; ++s) { cst[s][0] = 0.0f; cst[s][1] = 0.0f; }
    __syncthreads();

    // ================= phase 2: LSTM2 (relu) =================
    for (int t = 0; t < T; ++t) {
        u64 acc[8][4];
#pragma unroll
        for (int s = 0; s < 8; ++s)
#pragma unroll
            for (int r = 0; r < 4; ++r) acc[s][r] = bg2[r];

        gemm2(dsh + t * (DMLP * S), W2p, DMLP, sg8, ug8, acc);
        if (t > 0) gemm2(hs, Up, H, sg8, ug8, acc);

        float hh0[8], hh1[8];
#pragma unroll
        for (int s = 0; s < 8; ++s) {
            float val[8];
            UNPACK2(val[0], val[1], acc[s][0]);
            UNPACK2(val[2], val[3], acc[s][1]);
            UNPACK2(val[4], val[5], acc[s][2]);
            UNPACK2(val[6], val[7], acc[s][3]);
#pragma unroll
            for (int e = 0; e < 2; ++e) {
                const float ig = sigm(val[0 + e]);
                const float fg = sigm(val[2 + e]);
                const float gg = fmaxf(val[4 + e], 0.0f);   // relu activation
                const float og = sigm(val[6 + e]);
                const float cc = fmaf(fg, cst[s][e], ig * gg);
                cst[s][e] = cc;
                const float hv = og * fmaxf(cc, 0.0f);
                if (e == 0) hh0[s] = hv; else hh1[s] = hv;
            }
        }
        __syncthreads();
        *reinterpret_cast<float4*>(hs + u0 * 64 + sg8)           = make_float4(hh0[0], hh0[1], hh0[2], hh0[3]);
        *reinterpret_cast<float4*>(hs + u0 * 64 + sg8 + 4)       = make_float4(hh0[4], hh0[5], hh0[6], hh0[7]);
        *reinterpret_cast<float4*>(hs + (u0 + 1) * 64 + sg8)     = make_float4(hh1[0], hh1[1], hh1[2], hh1[3]);
        *reinterpret_cast<float4*>(hs + (u0 + 1) * 64 + sg8 + 4) = make_float4(hh1[4], hh1[5], hh1[6], hh1[7]);
        __syncthreads();
    }

    // ================= head: out = h2_last @ Wf + bf =================
    float* outg = out + (size_t)blockIdx.x * (S * DOUT);
    {
        const int s = tid >> 2, j = tid & 3;   // 64 samples x 4 outputs = 256
        float a = bfs[j];
#pragma unroll 8
        for (int k = 0; k < H; ++k)
            a = fmaf(hs[k * 64 + s], Wfs[k * DOUT + j], a);
        outg[s * DOUT + j] = a;
    }
}

extern "C" void kernel_launch(void* const* d_in, const int* in_sizes, int n_in,
                              void* d_out, int out_size) {
    (void)in_sizes; (void)n_in; (void)out_size;
    const float* x  = (const float*)d_in[0];
    const float* W1 = (const float*)d_in[1];
    const float* U1 = (const float*)d_in[2];
    const float* b1 = (const float*)d_in[3];
    const float* Wd = (const float*)d_in[4];
    const float* bd = (const float*)d_in[5];
    const float* W2 = (const float*)d_in[6];
    const float* U2 = (const float*)d_in[7];
    const float* b2 = (const float*)d_in[8];
    const float* Wf = (const float*)d_in[9];
    const float* bf = (const float*)d_in[10];
    float* out = (float*)d_out;

    cudaFuncSetAttribute(rnn_kernel, cudaFuncAttributeMaxDynamicSharedMemorySize, SMEM_BYTES);
    rnn_kernel<<<NCTA, THREADS, SMEM_BYTES>>>(x, W1, U1, b1, Wd, bd, W2, U2, b2, Wf, bf, out);
}